// round 10
// baseline (speedup 1.0000x reference)
#include <cuda_runtime.h>
#include <math.h>
#include <stdint.h>

// Problem constants
#define BB     2
#define LL     1024
#define HH     768
#define NHEADS 12
#define NE     24
#define MM     3
#define NC     2
#define CWW    8
#define BLK    64
#define NCLS   97
#define KB     12              // H / BLOCK
#define QTOT   (HH*BLK)        // 49152
#define NS     (BB*NE*NE)      // 1152
#define NPAD   128
#define KSL    12              // k-slices in logits kernel (one 64x64 block each)

typedef unsigned long long u64;

// ---- packed f32x2 helpers (FFMA2 path: only reachable via PTX) ----
__device__ __forceinline__ u64 pk2(float a, float b){
    u64 d; asm("mov.b64 %0, {%1, %2};" : "=l"(d) : "f"(a), "f"(b)); return d;
}
__device__ __forceinline__ u64 fma2(u64 a, u64 b, u64 c){
    u64 d; asm("fma.rn.f32x2 %0, %1, %2, %3;" : "=l"(d) : "l"(a), "l"(b), "l"(c)); return d;
}
__device__ __forceinline__ u64 mul2(u64 a, u64 b){
    u64 d; asm("mul.rn.f32x2 %0, %1, %2;" : "=l"(d) : "l"(a), "l"(b)); return d;
}
__device__ __forceinline__ float2 up2(u64 v){
    float2 r; asm("mov.b64 {%0, %1}, %2;" : "=f"(r.x), "=f"(r.y) : "l"(v)); return r;
}

// ---------------- device scratch (no runtime allocation allowed) ----------------
__device__ float g_eatt[BB*NE*NHEADS*LL];       // (b,e,h,l)  mean over mentions
__device__ float g_eemb[BB*NE*HH];              // logsumexp entity embedding
__device__ float g_ht[BB*NE*NE*LL];             // normalized relu attention product
__device__ float g_rs[(size_t)NS*HH];           // context vectors
__device__ float g_Ah[BB*NE*HH];                // e_emb @ Wh1^T + b_head
__device__ float g_At[BB*NE*HH];                // e_emb @ Wt1^T + b_tail
__device__ float g_zh[(size_t)NS*HH];
__device__ float g_zt[(size_t)NS*HH];
__device__ float g_WclsT[HH*NPAD];              // W_cls transposed, n-padded to 128
__device__ float g_Wc[(size_t)QTOT*NPAD];       // folded W_cls @ W_proj, layout [q][n]
__device__ float g_part[(size_t)KSL*NS*NCLS];   // logits partial sums per k-slice

// ---------------- Kernel 1: entity gather / gate / coref / logsumexp ----------------
__global__ void k_entity(const float* __restrict__ seq, const float* __restrict__ att,
                         const int* __restrict__ mst, const int* __restrict__ cst)
{
    int be  = blockIdx.x;           // b*NE + e
    int b   = be / NE;
    int tid = threadIdx.x;

    __shared__ float s_att[LL];
    __shared__ float s_gate[NC*CWW];
    __shared__ float s_red[256];
    __shared__ int   s_p[MM];
    __shared__ int   s_c[NC];

    if (tid < MM) s_p[tid] = mst[be*MM + tid] + 1;      // OFFSET = 1
    if (tid >= 32 && tid < 32+NC) s_c[tid-32] = cst[be*NC + (tid-32)];
    __syncthreads();

    int p0 = s_p[0], p1 = s_p[1], p2 = s_p[2];
    const float* ab = att + (size_t)b*NHEADS*LL*LL;

    for (int h = 0; h < NHEADS; ++h) {
        const float* r0 = ab + ((size_t)h*LL + p0)*LL;
        const float* r1 = ab + ((size_t)h*LL + p1)*LL;
        const float* r2 = ab + ((size_t)h*LL + p2)*LL;
        float* eo = g_eatt + ((size_t)be*NHEADS + h)*LL;
        for (int l = tid; l < LL; l += 256) {
            float v = (r0[l] + r1[l] + r2[l]) * (1.0f/3.0f);
            eo[l] = v;
            if (h == 0) s_att[l] = v; else s_att[l] += v;
        }
    }
    __syncthreads();

    float lsum = 0.f;
    for (int l = tid; l < LL; l += 256) lsum += s_att[l];
    s_red[tid] = lsum;
    __syncthreads();
    for (int off = 128; off > 0; off >>= 1) {
        if (tid < off) s_red[tid] += s_red[tid+off];
        __syncthreads();
    }
    float inv = 1.0f / s_red[0];

    if (tid < NC*CWW) {
        int c = tid / CWW, w = tid % CWW;
        s_gate[tid] = s_att[s_c[c] + w] * inv;
    }
    __syncthreads();

    const float* sb = seq + (size_t)b*LL*HH;
    int c0 = s_c[0], c1 = s_c[1];
    for (int d = tid; d < HH; d += 256) {
        float v0 = sb[(size_t)p0*HH + d];
        float v1 = sb[(size_t)p1*HH + d];
        float v2 = sb[(size_t)p2*HH + d];
        float v3 = 0.f, v4 = 0.f;
        #pragma unroll
        for (int w = 0; w < CWW; ++w) {
            v3 += s_gate[w]       * sb[(size_t)(c0+w)*HH + d];
            v4 += s_gate[CWW+w]   * sb[(size_t)(c1+w)*HH + d];
        }
        float mx = fmaxf(fmaxf(fmaxf(v0,v1), fmaxf(v2,v3)), v4);
        float s  = expf(v0-mx)+expf(v1-mx)+expf(v2-mx)+expf(v3-mx)+expf(v4-mx);
        g_eemb[(size_t)be*HH + d] = mx + logf(s);
    }
}

// ---------------- Kernel 2: ht = norm(relu(e_att . e_att^T over heads)) ----------------
__global__ void k_ht()
{
    int bef = blockIdx.x;                   // b*NE*NE + e*NE + f
    int b = bef / (NE*NE);
    int ef = bef % (NE*NE);
    int e = ef / NE, f = ef % NE;
    const float* pe = g_eatt + (size_t)(b*NE+e)*NHEADS*LL;
    const float* pf = g_eatt + (size_t)(b*NE+f)*NHEADS*LL;
    int tid = threadIdx.x;
    __shared__ float s_red[256];

    float v[4];
    float lsum = 0.f;
    #pragma unroll
    for (int r = 0; r < 4; ++r) {
        int l = r*256 + tid;
        float acc = 0.f;
        #pragma unroll
        for (int h = 0; h < NHEADS; ++h)
            acc += pe[h*LL + l] * pf[h*LL + l];
        v[r] = fmaxf(acc, 0.f);
        lsum += v[r];
    }
    s_red[tid] = lsum;
    __syncthreads();
    for (int off = 128; off > 0; off >>= 1) {
        if (tid < off) s_red[tid] += s_red[tid+off];
        __syncthreads();
    }
    float invn = 1.0f / (s_red[0] + 1e-10f);
    float* out = g_ht + (size_t)bef*LL;
    #pragma unroll
    for (int r = 0; r < 4; ++r) out[r*256 + tid] = v[r] * invn;
}

// ---------------- Kernel 3: rs[b] = ht[b] (576x1024) @ seq[b] (1024x768) ----------------
// FFMA2 microkernel: m-rows paired via LDS.64 broadcast, B cols packed via mov.b64.
__global__ void k_rs(const float* __restrict__ seq)
{
    const int BM=64, BN=64, BK=16;
    int bm = blockIdx.x, bn = blockIdx.y, b = blockIdx.z;
    const float* A  = g_ht + (size_t)b*NE*NE*LL;
    const float* Bm = seq  + (size_t)b*LL*HH;
    __shared__ float As[BK][BM];
    __shared__ float Bs[BK][BN];
    int tid = threadIdx.x;
    int tx = tid % 16, ty = tid / 16;
    int arow = tid / 4,  acol4 = (tid % 4) * 4;
    int brow = tid / 16, bcol4 = (tid % 16) * 4;
    u64 acc2[2][4] = {};     // [m-pair i2][n j]: lo=row ty*4+2i2, hi=+1

    for (int k0 = 0; k0 < LL; k0 += BK) {
        float4 a4 = *(const float4*)(A  + (size_t)(bm*BM + arow)*LL + k0 + acol4);
        float4 b4 = *(const float4*)(Bm + (size_t)(k0 + brow)*HH + bn*BN + bcol4);
        As[acol4+0][arow] = a4.x; As[acol4+1][arow] = a4.y;
        As[acol4+2][arow] = a4.z; As[acol4+3][arow] = a4.w;
        *(float4*)&Bs[brow][bcol4] = b4;
        __syncthreads();
        #pragma unroll
        for (int kk = 0; kk < BK; ++kk) {
            u64 av01 = *(const u64*)&As[kk][ty*4];
            u64 av23 = *(const u64*)&As[kk][ty*4+2];
            float4 bv = *(float4*)&Bs[kk][tx*4];
            u64 b0 = pk2(bv.x,bv.x), b1 = pk2(bv.y,bv.y);
            u64 b2 = pk2(bv.z,bv.z), b3 = pk2(bv.w,bv.w);
            acc2[0][0]=fma2(av01,b0,acc2[0][0]); acc2[0][1]=fma2(av01,b1,acc2[0][1]);
            acc2[0][2]=fma2(av01,b2,acc2[0][2]); acc2[0][3]=fma2(av01,b3,acc2[0][3]);
            acc2[1][0]=fma2(av23,b0,acc2[1][0]); acc2[1][1]=fma2(av23,b1,acc2[1][1]);
            acc2[1][2]=fma2(av23,b2,acc2[1][2]); acc2[1][3]=fma2(av23,b3,acc2[1][3]);
        }
        __syncthreads();
    }
    #pragma unroll
    for (int i2 = 0; i2 < 2; ++i2) {
        float2 u0=up2(acc2[i2][0]), u1=up2(acc2[i2][1]), u2=up2(acc2[i2][2]), u3=up2(acc2[i2][3]);
        int r0 = bm*BM + ty*4 + 2*i2;
        *(float4*)(g_rs + (size_t)(b*NE*NE + r0  )*HH + bn*BN + tx*4) = make_float4(u0.x,u1.x,u2.x,u3.x);
        *(float4*)(g_rs + (size_t)(b*NE*NE + r0+1)*HH + bn*BN + tx*4) = make_float4(u0.y,u1.y,u2.y,u3.y);
    }
}

// ---------------- Kernel 4a: Ah/At = e_emb @ W1^T + bias (tiled GEMM, prefetched) -------
__global__ void k_AhAt(const float* __restrict__ Wh, const float* __restrict__ bh,
                       const float* __restrict__ Wt, const float* __restrict__ bt)
{
    const int BN = 64, BK = 16;
    int d0    = blockIdx.x * BN;
    int which = blockIdx.y;
    const float* W    = which ? Wt : Wh;
    const float* bias = which ? bt : bh;
    float* Out        = which ? g_At : g_Ah;

    __shared__ float e_s[BK][48+2];     // transposed: e_s[k][be]
    __shared__ float W_s[BK][BN+4];     // transposed: W_s[k][d]

    int tid = threadIdx.x;
    int tx = tid % 16, ty = tid / 16;   // tx -> 4 d's, ty -> 3 entities
    float acc[3][4] = {};

    int er = tid / 4,  ec4 = (tid % 4) * 4;
    int wr = tid / 4,  wc4 = (tid % 4) * 4;

    float4 e4 = make_float4(0,0,0,0), w4;
    if (tid < 192) e4 = *(const float4*)(g_eemb + (size_t)er*HH + ec4);
    w4 = *(const float4*)(W + (size_t)(d0+wr)*(2*HH) + wc4);

    for (int k0 = 0; k0 < HH; k0 += BK) {
        if (tid < 192) {
            e_s[ec4+0][er]=e4.x; e_s[ec4+1][er]=e4.y; e_s[ec4+2][er]=e4.z; e_s[ec4+3][er]=e4.w;
        }
        W_s[wc4+0][wr]=w4.x; W_s[wc4+1][wr]=w4.y; W_s[wc4+2][wr]=w4.z; W_s[wc4+3][wr]=w4.w;
        __syncthreads();
        if (k0 + BK < HH) {   // prefetch next tile while computing this one
            if (tid < 192) e4 = *(const float4*)(g_eemb + (size_t)er*HH + k0 + BK + ec4);
            w4 = *(const float4*)(W + (size_t)(d0+wr)*(2*HH) + k0 + BK + wc4);
        }
        #pragma unroll
        for (int kk = 0; kk < BK; ++kk) {
            float4 wv = *(float4*)&W_s[kk][tx*4];
            #pragma unroll
            for (int si = 0; si < 3; ++si) {
                float a = e_s[kk][ty*3 + si];
                acc[si][0]+=a*wv.x; acc[si][1]+=a*wv.y; acc[si][2]+=a*wv.z; acc[si][3]+=a*wv.w;
            }
        }
        __syncthreads();
    }
    #pragma unroll
    for (int si = 0; si < 3; ++si) {
        int be = ty*3 + si;
        #pragma unroll
        for (int c = 0; c < 4; ++c) {
            int d = d0 + tx*4 + c;
            Out[(size_t)be*HH + d] = acc[si][c] + bias[d];
        }
    }
}

// ---------------- Kernel 4b: [zh|zt] = tanh(rs @ W2^T + A), FFMA2 ----------------------
__global__ void k_zhzt(const float* __restrict__ Wh, const float* __restrict__ Wt)
{
    const int BM=64, BN=64, BK=16;
    int bm = blockIdx.x, bn = blockIdx.y;
    bool isHead = (bn < HH/BN);
    const float* W = isHead ? Wh : Wt;
    int ncol0 = (isHead ? bn : bn - HH/BN) * BN;

    __shared__ float As[BK][BM];
    __shared__ float Bs[BK][BN];
    int tid = threadIdx.x;
    int tx = tid % 16, ty = tid / 16;
    int arow = tid / 4, acol4 = (tid % 4) * 4;
    u64 acc2[2][4] = {};     // [m-pair][n]

    for (int k0 = 0; k0 < HH; k0 += BK) {
        float4 a4 = *(const float4*)(g_rs + (size_t)(bm*BM + arow)*HH + k0 + acol4);
        float4 b4 = *(const float4*)(W + (size_t)(ncol0 + arow)*(2*HH) + HH + k0 + acol4);
        As[acol4+0][arow] = a4.x; As[acol4+1][arow] = a4.y;
        As[acol4+2][arow] = a4.z; As[acol4+3][arow] = a4.w;
        Bs[acol4+0][arow] = b4.x; Bs[acol4+1][arow] = b4.y;
        Bs[acol4+2][arow] = b4.z; Bs[acol4+3][arow] = b4.w;
        __syncthreads();
        #pragma unroll
        for (int kk = 0; kk < BK; ++kk) {
            u64 av01 = *(const u64*)&As[kk][ty*4];
            u64 av23 = *(const u64*)&As[kk][ty*4+2];
            float4 bv = *(float4*)&Bs[kk][tx*4];
            u64 b0 = pk2(bv.x,bv.x), b1 = pk2(bv.y,bv.y);
            u64 b2 = pk2(bv.z,bv.z), b3 = pk2(bv.w,bv.w);
            acc2[0][0]=fma2(av01,b0,acc2[0][0]); acc2[0][1]=fma2(av01,b1,acc2[0][1]);
            acc2[0][2]=fma2(av01,b2,acc2[0][2]); acc2[0][3]=fma2(av01,b3,acc2[0][3]);
            acc2[1][0]=fma2(av23,b0,acc2[1][0]); acc2[1][1]=fma2(av23,b1,acc2[1][1]);
            acc2[1][2]=fma2(av23,b2,acc2[1][2]); acc2[1][3]=fma2(av23,b3,acc2[1][3]);
        }
        __syncthreads();
    }
    float* Z = isHead ? g_zh : g_zt;
    #pragma unroll
    for (int i2 = 0; i2 < 2; ++i2) {
        float2 u[4];
        u[0]=up2(acc2[i2][0]); u[1]=up2(acc2[i2][1]); u[2]=up2(acc2[i2][2]); u[3]=up2(acc2[i2][3]);
        #pragma unroll
        for (int half = 0; half < 2; ++half) {
            int s  = bm*BM + ty*4 + 2*i2 + half;
            int b  = s / (NE*NE);
            int ef = s % (NE*NE);
            int e  = ef / NE, f = ef % NE;
            const float* Avec = isHead ? (g_Ah + (size_t)(b*NE+e)*HH)
                                       : (g_At + (size_t)(b*NE+f)*HH);
            #pragma unroll
            for (int j = 0; j < 4; ++j) {
                int col = ncol0 + tx*4 + j;
                float v = half ? u[j].y : u[j].x;
                Z[(size_t)s*HH + col] = tanhf(v + Avec[col]);
            }
        }
    }
}

// ---------------- Kernel 5a: transpose W_cls -> [d][n] padded to 128 -------------------
__global__ void k_wclsT(const float* __restrict__ Wcls)
{
    int idx = blockIdx.x*256 + threadIdx.x;
    if (idx >= HH*NPAD) return;
    int d = idx / NPAD, n = idx % NPAD;
    g_WclsT[idx] = (n < NCLS) ? Wcls[(size_t)n*HH + d] : 0.f;
}

// ---------------- Kernel 5b: Wc[q][n] = sum_d W_proj[d][q] * W_cls[n][d], FFMA2 --------
__global__ void k_wc(const float* __restrict__ Wproj)
{
    const int QT = 64, DB = 16;
    int q0 = blockIdx.x * QT;
    int tid = threadIdx.x, tx = tid % 32, ty = tid / 32;
    __shared__ float Wp_s[DB][QT];
    __shared__ float Wt_s[DB][NPAD];
    u64 acc2[4][4] = {};      // [q-pair r2][class c]: lo=row ty*8+2r2, hi=+1

    int pr = tid / 16, pc4 = (tid % 16) * 4;
    int cr = tid / 32, cc4 = (tid % 32) * 4;

    for (int d0 = 0; d0 < HH; d0 += DB) {
        *(float4*)&Wp_s[pr][pc4]   = *(const float4*)(Wproj + (size_t)(d0+pr)*QTOT + q0 + pc4);
        *(float4*)&Wt_s[cr][cc4]   = *(const float4*)(g_WclsT + (size_t)(d0+cr)*NPAD + cc4);
        *(float4*)&Wt_s[cr+8][cc4] = *(const float4*)(g_WclsT + (size_t)(d0+cr+8)*NPAD + cc4);
        __syncthreads();
        #pragma unroll
        for (int dd = 0; dd < DB; ++dd) {
            u64 wq[4];       // q-row pairs, free via LDS.64 broadcast
            wq[0] = *(const u64*)&Wp_s[dd][ty*8];
            wq[1] = *(const u64*)&Wp_s[dd][ty*8+2];
            wq[2] = *(const u64*)&Wp_s[dd][ty*8+4];
            wq[3] = *(const u64*)&Wp_s[dd][ty*8+6];
            float4 wn = *(float4*)&Wt_s[dd][tx*4];
            u64 n0 = pk2(wn.x,wn.x), n1 = pk2(wn.y,wn.y);
            u64 n2 = pk2(wn.z,wn.z), n3 = pk2(wn.w,wn.w);
            #pragma unroll
            for (int r2 = 0; r2 < 4; ++r2) {
                acc2[r2][0] = fma2(wq[r2], n0, acc2[r2][0]);
                acc2[r2][1] = fma2(wq[r2], n1, acc2[r2][1]);
                acc2[r2][2] = fma2(wq[r2], n2, acc2[r2][2]);
                acc2[r2][3] = fma2(wq[r2], n3, acc2[r2][3]);
            }
        }
        __syncthreads();
    }
    #pragma unroll
    for (int r2 = 0; r2 < 4; ++r2) {
        float2 u0=up2(acc2[r2][0]), u1=up2(acc2[r2][1]), u2=up2(acc2[r2][2]), u3=up2(acc2[r2][3]);
        int row = q0 + ty*8 + 2*r2;
        *(float4*)(g_Wc + (size_t)(row  )*NPAD + tx*4) = make_float4(u0.x,u1.x,u2.x,u3.x);
        *(float4*)(g_Wc + (size_t)(row+1)*NPAD + tx*4) = make_float4(u0.y,u1.y,u2.y,u3.y);
    }
}

// ---------------- Kernel 6: logits partials = (zh (x) zt) . Wc, FFMA2 ------------------
// Barrier-free mainloop. Samples paired via transposed smem (LDS.64 broadcast),
// w packed (w,w) on alu pipe. Grid (NS/32, KSL). Block 256 = 32 tx x 8 ty.
// Thread: samples ty*4..ty*4+3 (2 pairs) x classes tx*4..tx*4+3.
__global__ void k_logits()
{
    const int STR = 34;                  // even stride: 8B-aligned pairs, modest conflicts
    int s0 = blockIdx.x * 32;
    int k  = blockIdx.y;
    int tid = threadIdx.x, tx = tid % 32, ty = tid / 32;

    __shared__ float zh_t[BLK][STR];     // [i][sample]
    __shared__ float zt_t[BLK][STR];     // [j][sample]
    u64 acc2[2][4] = {};                 // [sample-pair p][class c]

    {   // stage: transpose 32x64 tiles of zh/zt into smem
        int r  = tid / 8;                // sample 0..31
        int c4 = (tid % 8) * 8;          // col 0,8,...,56
        const float* ph = g_zh + (size_t)(s0+r)*HH + k*BLK + c4;
        const float* pt = g_zt + (size_t)(s0+r)*HH + k*BLK + c4;
        float4 h0 = *(const float4*)(ph),   h1 = *(const float4*)(ph+4);
        float4 t0 = *(const float4*)(pt),   t1 = *(const float4*)(pt+4);
        zh_t[c4+0][r]=h0.x; zh_t[c4+1][r]=h0.y; zh_t[c4+2][r]=h0.z; zh_t[c4+3][r]=h0.w;
        zh_t[c4+4][r]=h1.x; zh_t[c4+5][r]=h1.y; zh_t[c4+6][r]=h1.z; zh_t[c4+7][r]=h1.w;
        zt_t[c4+0][r]=t0.x; zt_t[c4+1][r]=t0.y; zt_t[c4+2][r]=t0.z; zt_t[c4+3][r]=t0.w;
        zt_t[c4+4][r]=t1.x; zt_t[c4+5][r]=t1.y; zt_t[c4+6][r]=t1.z; zt_t[c4+7][r]=t1.w;
    }
    __syncthreads();

    const float* wbase = g_Wc + (size_t)(k*BLK)*BLK*NPAD + tx*4;

    for (int i = 0; i < BLK; ++i) {
        u64 zh2a = *(const u64*)&zh_t[i][ty*4];      // (s0',s1') pair, LDS.64 broadcast
        u64 zh2b = *(const u64*)&zh_t[i][ty*4+2];
        const float* wrow = wbase + (size_t)i*BLK*NPAD;
        #pragma unroll 4
        for (int j = 0; j < BLK; ++j) {
            u64 zt2a = *(const u64*)&zt_t[j][ty*4];
            u64 zt2b = *(const u64*)&zt_t[j][ty*4+2];
            u64 a2a = mul2(zh2a, zt2a);
            u64 a2b = mul2(zh2b, zt2b);
            float4 w = *(const float4*)(wrow + (size_t)j*NPAD);   // coalesced LDG.128
            u64 w0 = pk2(w.x,w.x), w1 = pk2(w.y,w.y);
            u64 w2 = pk2(w.z,w.z), w3 = pk2(w.w,w.w);
            acc2[0][0]=fma2(a2a,w0,acc2[0][0]); acc2[0][1]=fma2(a2a,w1,acc2[0][1]);
            acc2[0][2]=fma2(a2a,w2,acc2[0][2]); acc2[0][3]=fma2(a2a,w3,acc2[0][3]);
            acc2[1][0]=fma2(a2b,w0,acc2[1][0]); acc2[1][1]=fma2(a2b,w1,acc2[1][1]);
            acc2[1][2]=fma2(a2b,w2,acc2[1][2]); acc2[1][3]=fma2(a2b,w3,acc2[1][3]);
        }
    }

    float* pp = g_part + (size_t)k*NS*NCLS;
    #pragma unroll
    for (int p = 0; p < 2; ++p) {
        int s = s0 + ty*4 + 2*p;
        #pragma unroll
        for (int c = 0; c < 4; ++c) {
            int n = tx*4 + c;
            if (n < NCLS) {
                float2 v = up2(acc2[p][c]);
                pp[(size_t)s*NCLS + n]     = v.x;
                pp[(size_t)(s+1)*NCLS + n] = v.y;
            }
        }
    }
}

// ---------------- Kernel 7: reduce k-slice partials + bias -----------------------------
__global__ void k_reduce(const float* __restrict__ bcls, float* __restrict__ out)
{
    int idx = blockIdx.x*256 + threadIdx.x;
    if (idx >= NS*NCLS) return;
    int n = idx % NCLS;
    float v = bcls[n];
    #pragma unroll
    for (int sl = 0; sl < KSL; ++sl) v += g_part[(size_t)sl*NS*NCLS + idx];
    out[idx] = v;
}

// ---------------- launch --------------------------------------------------------------
extern "C" void kernel_launch(void* const* d_in, const int* in_sizes, int n_in,
                              void* d_out, int out_size)
{
    (void)in_sizes; (void)n_in; (void)out_size;
    const float* seq   = (const float*)d_in[0];
    const float* att   = (const float*)d_in[1];
    const int*   mst   = (const int*)  d_in[2];
    const int*   cst   = (const int*)  d_in[3];
    const float* Wh    = (const float*)d_in[4];
    const float* bh    = (const float*)d_in[5];
    const float* Wt    = (const float*)d_in[6];
    const float* bt    = (const float*)d_in[7];
    const float* Wproj = (const float*)d_in[8];
    const float* Wcls  = (const float*)d_in[9];
    const float* bcls  = (const float*)d_in[10];
    float* out = (float*)d_out;

    k_entity<<<BB*NE, 256>>>(seq, att, mst, cst);
    k_ht<<<BB*NE*NE, 256>>>();
    {
        dim3 g(NE*NE/64, HH/64, BB);            // 9 x 12 x 2
        k_rs<<<g, 256>>>(seq);
    }
    {
        dim3 g(HH/64, 2);                       // 12 x 2
        k_AhAt<<<g, 256>>>(Wh, bh, Wt, bt);
    }
    {
        dim3 g(NS/64, (2*HH)/64);               // 18 x 24
        k_zhzt<<<g, 256>>>(Wh, Wt);
    }
    k_wclsT<<<(HH*NPAD)/256, 256>>>(Wcls);
    k_wc<<<QTOT/64, 256>>>(Wproj);              // 768 CTAs
    {
        dim3 g(NS/32, KSL);                     // 36 x 12 = 432 CTAs
        k_logits<<<g, 256>>>();
    }
    k_reduce<<<(NS*NCLS + 255)/256, 256>>>(bcls, out);
}

// round 12
// speedup vs baseline: 1.0530x; 1.0530x over previous
#include <cuda_runtime.h>
#include <math.h>
#include <stdint.h>

// Problem constants
#define BB     2
#define LL     1024
#define HH     768
#define NHEADS 12
#define NE     24
#define MM     3
#define NC     2
#define CWW    8
#define BLK    64
#define NCLS   97
#define KB     12              // H / BLOCK
#define QTOT   (HH*BLK)        // 49152
#define NS     (BB*NE*NE)      // 1152
#define NPAD   128
#define KSL    12              // k-slices in logits kernel (one 64x64 block each)

// ---------------- device scratch (no runtime allocation allowed) ----------------
__device__ float g_eatt[BB*NE*NHEADS*LL];       // (b,e,h,l)  mean over mentions
__device__ float g_eemb[BB*NE*HH];              // logsumexp entity embedding
__device__ float g_ht[BB*NE*NE*LL];             // normalized relu attention product
__device__ float g_rs[(size_t)NS*HH];           // context vectors
__device__ float g_Ah[BB*NE*HH];                // e_emb @ Wh1^T + b_head
__device__ float g_At[BB*NE*HH];                // e_emb @ Wt1^T + b_tail
__device__ float g_zh[(size_t)NS*HH];
__device__ float g_zt[(size_t)NS*HH];
__device__ float g_WclsT[HH*NPAD];              // W_cls transposed, n-padded to 128
__device__ float g_Wc[(size_t)QTOT*NPAD];       // folded W_cls @ W_proj, layout [q][n]
__device__ float g_part[(size_t)KSL*NS*NCLS];   // logits partial sums per k-slice

// ---------------- Kernel 1: entity gather / gate / coref / logsumexp ----------------
__global__ void k_entity(const float* __restrict__ seq, const float* __restrict__ att,
                         const int* __restrict__ mst, const int* __restrict__ cst)
{
    int be  = blockIdx.x;           // b*NE + e
    int b   = be / NE;
    int tid = threadIdx.x;

    __shared__ float s_att[LL];
    __shared__ float s_gate[NC*CWW];
    __shared__ float s_red[256];
    __shared__ int   s_p[MM];
    __shared__ int   s_c[NC];

    if (tid < MM) s_p[tid] = mst[be*MM + tid] + 1;      // OFFSET = 1
    if (tid >= 32 && tid < 32+NC) s_c[tid-32] = cst[be*NC + (tid-32)];
    __syncthreads();

    int p0 = s_p[0], p1 = s_p[1], p2 = s_p[2];
    const float* ab = att + (size_t)b*NHEADS*LL*LL;

    for (int h = 0; h < NHEADS; ++h) {
        const float* r0 = ab + ((size_t)h*LL + p0)*LL;
        const float* r1 = ab + ((size_t)h*LL + p1)*LL;
        const float* r2 = ab + ((size_t)h*LL + p2)*LL;
        float* eo = g_eatt + ((size_t)be*NHEADS + h)*LL;
        for (int l = tid; l < LL; l += 256) {
            float v = (r0[l] + r1[l] + r2[l]) * (1.0f/3.0f);
            eo[l] = v;
            if (h == 0) s_att[l] = v; else s_att[l] += v;
        }
    }
    __syncthreads();

    float lsum = 0.f;
    for (int l = tid; l < LL; l += 256) lsum += s_att[l];
    s_red[tid] = lsum;
    __syncthreads();
    for (int off = 128; off > 0; off >>= 1) {
        if (tid < off) s_red[tid] += s_red[tid+off];
        __syncthreads();
    }
    float inv = 1.0f / s_red[0];

    if (tid < NC*CWW) {
        int c = tid / CWW, w = tid % CWW;
        s_gate[tid] = s_att[s_c[c] + w] * inv;
    }
    __syncthreads();

    const float* sb = seq + (size_t)b*LL*HH;
    int c0 = s_c[0], c1 = s_c[1];
    for (int d = tid; d < HH; d += 256) {
        float v0 = sb[(size_t)p0*HH + d];
        float v1 = sb[(size_t)p1*HH + d];
        float v2 = sb[(size_t)p2*HH + d];
        float v3 = 0.f, v4 = 0.f;
        #pragma unroll
        for (int w = 0; w < CWW; ++w) {
            v3 += s_gate[w]       * sb[(size_t)(c0+w)*HH + d];
            v4 += s_gate[CWW+w]   * sb[(size_t)(c1+w)*HH + d];
        }
        float mx = fmaxf(fmaxf(fmaxf(v0,v1), fmaxf(v2,v3)), v4);
        float s  = expf(v0-mx)+expf(v1-mx)+expf(v2-mx)+expf(v3-mx)+expf(v4-mx);
        g_eemb[(size_t)be*HH + d] = mx + logf(s);
    }
}

// ---------------- Kernel 2: ht = norm(relu(e_att . e_att^T over heads)) ----------------
__global__ void k_ht()
{
    int bef = blockIdx.x;                   // b*NE*NE + e*NE + f
    int b = bef / (NE*NE);
    int ef = bef % (NE*NE);
    int e = ef / NE, f = ef % NE;
    const float* pe = g_eatt + (size_t)(b*NE+e)*NHEADS*LL;
    const float* pf = g_eatt + (size_t)(b*NE+f)*NHEADS*LL;
    int tid = threadIdx.x;
    __shared__ float s_red[256];

    float v[4];
    float lsum = 0.f;
    #pragma unroll
    for (int r = 0; r < 4; ++r) {
        int l = r*256 + tid;
        float acc = 0.f;
        #pragma unroll
        for (int h = 0; h < NHEADS; ++h)
            acc += pe[h*LL + l] * pf[h*LL + l];
        v[r] = fmaxf(acc, 0.f);
        lsum += v[r];
    }
    s_red[tid] = lsum;
    __syncthreads();
    for (int off = 128; off > 0; off >>= 1) {
        if (tid < off) s_red[tid] += s_red[tid+off];
        __syncthreads();
    }
    float invn = 1.0f / (s_red[0] + 1e-10f);
    float* out = g_ht + (size_t)bef*LL;
    #pragma unroll
    for (int r = 0; r < 4; ++r) out[r*256 + tid] = v[r] * invn;
}

// ---------------- Kernel 3: rs[b] = ht[b] (576x1024) @ seq[b] (1024x768) ----------------
__global__ void k_rs(const float* __restrict__ seq)
{
    const int BM=64, BN=64, BK=16;
    int bm = blockIdx.x, bn = blockIdx.y, b = blockIdx.z;
    const float* A  = g_ht + (size_t)b*NE*NE*LL;
    const float* Bm = seq  + (size_t)b*LL*HH;
    __shared__ float As[BK][BM];
    __shared__ float Bs[BK][BN];
    int tid = threadIdx.x;
    int tx = tid % 16, ty = tid / 16;
    int arow = tid / 4,  acol4 = (tid % 4) * 4;
    int brow = tid / 16, bcol4 = (tid % 16) * 4;
    float acc[4][4] = {};

    for (int k0 = 0; k0 < LL; k0 += BK) {
        float4 a4 = *(const float4*)(A  + (size_t)(bm*BM + arow)*LL + k0 + acol4);
        float4 b4 = *(const float4*)(Bm + (size_t)(k0 + brow)*HH + bn*BN + bcol4);
        As[acol4+0][arow] = a4.x; As[acol4+1][arow] = a4.y;
        As[acol4+2][arow] = a4.z; As[acol4+3][arow] = a4.w;
        *(float4*)&Bs[brow][bcol4] = b4;
        __syncthreads();
        #pragma unroll
        for (int kk = 0; kk < BK; ++kk) {
            float4 av = *(float4*)&As[kk][ty*4];
            float4 bv = *(float4*)&Bs[kk][tx*4];
            acc[0][0]+=av.x*bv.x; acc[0][1]+=av.x*bv.y; acc[0][2]+=av.x*bv.z; acc[0][3]+=av.x*bv.w;
            acc[1][0]+=av.y*bv.x; acc[1][1]+=av.y*bv.y; acc[1][2]+=av.y*bv.z; acc[1][3]+=av.y*bv.w;
            acc[2][0]+=av.z*bv.x; acc[2][1]+=av.z*bv.y; acc[2][2]+=av.z*bv.z; acc[2][3]+=av.z*bv.w;
            acc[3][0]+=av.w*bv.x; acc[3][1]+=av.w*bv.y; acc[3][2]+=av.w*bv.z; acc[3][3]+=av.w*bv.w;
        }
        __syncthreads();
    }
    #pragma unroll
    for (int i = 0; i < 4; ++i) {
        float4 o = make_float4(acc[i][0], acc[i][1], acc[i][2], acc[i][3]);
        *(float4*)(g_rs + (size_t)(b*NE*NE + bm*BM + ty*4 + i)*HH + bn*BN + tx*4) = o;
    }
}

// ---------------- Kernel 4a: Ah/At = e_emb @ W1^T + bias (tiled GEMM, prefetched) -------
__global__ void k_AhAt(const float* __restrict__ Wh, const float* __restrict__ bh,
                       const float* __restrict__ Wt, const float* __restrict__ bt)
{
    const int BN = 64, BK = 16;
    int d0    = blockIdx.x * BN;
    int which = blockIdx.y;
    const float* W    = which ? Wt : Wh;
    const float* bias = which ? bt : bh;
    float* Out        = which ? g_At : g_Ah;

    __shared__ float e_s[BK][48+2];     // transposed: e_s[k][be]
    __shared__ float W_s[BK][BN+4];     // transposed: W_s[k][d]

    int tid = threadIdx.x;
    int tx = tid % 16, ty = tid / 16;   // tx -> 4 d's, ty -> 3 entities
    float acc[3][4] = {};

    int er = tid / 4,  ec4 = (tid % 4) * 4;
    int wr = tid / 4,  wc4 = (tid % 4) * 4;

    float4 e4 = make_float4(0,0,0,0), w4;
    if (tid < 192) e4 = *(const float4*)(g_eemb + (size_t)er*HH + ec4);
    w4 = *(const float4*)(W + (size_t)(d0+wr)*(2*HH) + wc4);

    for (int k0 = 0; k0 < HH; k0 += BK) {
        if (tid < 192) {
            e_s[ec4+0][er]=e4.x; e_s[ec4+1][er]=e4.y; e_s[ec4+2][er]=e4.z; e_s[ec4+3][er]=e4.w;
        }
        W_s[wc4+0][wr]=w4.x; W_s[wc4+1][wr]=w4.y; W_s[wc4+2][wr]=w4.z; W_s[wc4+3][wr]=w4.w;
        __syncthreads();
        if (k0 + BK < HH) {   // prefetch next tile while computing this one
            if (tid < 192) e4 = *(const float4*)(g_eemb + (size_t)er*HH + k0 + BK + ec4);
            w4 = *(const float4*)(W + (size_t)(d0+wr)*(2*HH) + k0 + BK + wc4);
        }
        #pragma unroll
        for (int kk = 0; kk < BK; ++kk) {
            float4 wv = *(float4*)&W_s[kk][tx*4];
            #pragma unroll
            for (int si = 0; si < 3; ++si) {
                float a = e_s[kk][ty*3 + si];
                acc[si][0]+=a*wv.x; acc[si][1]+=a*wv.y; acc[si][2]+=a*wv.z; acc[si][3]+=a*wv.w;
            }
        }
        __syncthreads();
    }
    #pragma unroll
    for (int si = 0; si < 3; ++si) {
        int be = ty*3 + si;
        #pragma unroll
        for (int c = 0; c < 4; ++c) {
            int d = d0 + tx*4 + c;
            Out[(size_t)be*HH + d] = acc[si][c] + bias[d];
        }
    }
}

// ---------------- Kernel 4b: [zh|zt] = tanh(rs @ W2^T + A) -----------------------------
__global__ void k_zhzt(const float* __restrict__ Wh, const float* __restrict__ Wt)
{
    const int BM=64, BN=64, BK=16;
    int bm = blockIdx.x, bn = blockIdx.y;
    bool isHead = (bn < HH/BN);
    const float* W = isHead ? Wh : Wt;
    int ncol0 = (isHead ? bn : bn - HH/BN) * BN;

    __shared__ float As[BK][BM];
    __shared__ float Bs[BK][BN];
    int tid = threadIdx.x;
    int tx = tid % 16, ty = tid / 16;
    int arow = tid / 4, acol4 = (tid % 4) * 4;
    float acc[4][4] = {};

    for (int k0 = 0; k0 < HH; k0 += BK) {
        float4 a4 = *(const float4*)(g_rs + (size_t)(bm*BM + arow)*HH + k0 + acol4);
        float4 b4 = *(const float4*)(W + (size_t)(ncol0 + arow)*(2*HH) + HH + k0 + acol4);
        As[acol4+0][arow] = a4.x; As[acol4+1][arow] = a4.y;
        As[acol4+2][arow] = a4.z; As[acol4+3][arow] = a4.w;
        Bs[acol4+0][arow] = b4.x; Bs[acol4+1][arow] = b4.y;
        Bs[acol4+2][arow] = b4.z; Bs[acol4+3][arow] = b4.w;
        __syncthreads();
        #pragma unroll
        for (int kk = 0; kk < BK; ++kk) {
            float4 av = *(float4*)&As[kk][ty*4];
            float4 bv = *(float4*)&Bs[kk][tx*4];
            acc[0][0]+=av.x*bv.x; acc[0][1]+=av.x*bv.y; acc[0][2]+=av.x*bv.z; acc[0][3]+=av.x*bv.w;
            acc[1][0]+=av.y*bv.x; acc[1][1]+=av.y*bv.y; acc[1][2]+=av.y*bv.z; acc[1][3]+=av.y*bv.w;
            acc[2][0]+=av.z*bv.x; acc[2][1]+=av.z*bv.y; acc[2][2]+=av.z*bv.z; acc[2][3]+=av.z*bv.w;
            acc[3][0]+=av.w*bv.x; acc[3][1]+=av.w*bv.y; acc[3][2]+=av.w*bv.z; acc[3][3]+=av.w*bv.w;
        }
        __syncthreads();
    }
    float* Z = isHead ? g_zh : g_zt;
    #pragma unroll
    for (int i = 0; i < 4; ++i) {
        int s  = bm*BM + ty*4 + i;
        int b  = s / (NE*NE);
        int ef = s % (NE*NE);
        int e  = ef / NE, f = ef % NE;
        const float* Avec = isHead ? (g_Ah + (size_t)(b*NE+e)*HH)
                                   : (g_At + (size_t)(b*NE+f)*HH);
        #pragma unroll
        for (int j = 0; j < 4; ++j) {
            int col = ncol0 + tx*4 + j;
            Z[(size_t)s*HH + col] = tanhf(acc[i][j] + Avec[col]);
        }
    }
}

// ---------------- Kernel 5a: transpose W_cls -> [d][n] padded to 128 -------------------
__global__ void k_wclsT(const float* __restrict__ Wcls)
{
    int idx = blockIdx.x*256 + threadIdx.x;
    if (idx >= HH*NPAD) return;
    int d = idx / NPAD, n = idx % NPAD;
    g_WclsT[idx] = (n < NCLS) ? Wcls[(size_t)n*HH + d] : 0.f;
}

// ---------------- Kernel 5b: Wc[q][n] = sum_d W_proj[d][q] * W_cls[n][d] ---------------
// Register double-buffer prefetch hides gmem latency across the barrier.
__global__ void k_wc(const float* __restrict__ Wproj)
{
    const int QT = 64, DB = 16;
    int q0 = blockIdx.x * QT;
    int tid = threadIdx.x, tx = tid % 32, ty = tid / 32;
    __shared__ float Wp_s[DB][QT];
    __shared__ float Wt_s[DB][NPAD];
    float acc[8][4] = {};

    int pr = tid / 16, pc4 = (tid % 16) * 4;    // Wp tile load map
    int cr = tid / 32, cc4 = (tid % 32) * 4;    // WclsT tile load map

    float4 a0 = *(const float4*)(Wproj   + (size_t)pr*QTOT + q0 + pc4);
    float4 b0 = *(const float4*)(g_WclsT + (size_t)cr*NPAD + cc4);
    float4 b1 = *(const float4*)(g_WclsT + (size_t)(cr+8)*NPAD + cc4);

    for (int d0 = 0; d0 < HH; d0 += DB) {
        *(float4*)&Wp_s[pr][pc4]   = a0;
        *(float4*)&Wt_s[cr][cc4]   = b0;
        *(float4*)&Wt_s[cr+8][cc4] = b1;
        __syncthreads();
        if (d0 + DB < HH) {   // prefetch next tile
            a0 = *(const float4*)(Wproj   + (size_t)(d0+DB+pr)*QTOT + q0 + pc4);
            b0 = *(const float4*)(g_WclsT + (size_t)(d0+DB+cr)*NPAD + cc4);
            b1 = *(const float4*)(g_WclsT + (size_t)(d0+DB+cr+8)*NPAD + cc4);
        }
        #pragma unroll
        for (int dd = 0; dd < DB; ++dd) {
            float4 wq0 = *(float4*)&Wp_s[dd][ty*8];
            float4 wq1 = *(float4*)&Wp_s[dd][ty*8+4];
            float4 wn  = *(float4*)&Wt_s[dd][tx*4];
            float wq[8] = {wq0.x,wq0.y,wq0.z,wq0.w,wq1.x,wq1.y,wq1.z,wq1.w};
            #pragma unroll
            for (int r = 0; r < 8; ++r) {
                acc[r][0] += wq[r]*wn.x;
                acc[r][1] += wq[r]*wn.y;
                acc[r][2] += wq[r]*wn.z;
                acc[r][3] += wq[r]*wn.w;
            }
        }
        __syncthreads();
    }
    #pragma unroll
    for (int r = 0; r < 8; ++r) {
        float4 o = make_float4(acc[r][0], acc[r][1], acc[r][2], acc[r][3]);
        *(float4*)(g_Wc + (size_t)(q0 + ty*8 + r)*NPAD + tx*4) = o;
    }
}

// ---------------- Kernel 6: logits partials = (zh (x) zt) . Wc -------------------------
// Barrier-free mainloop; 128 threads = 16 tx (8 classes each) x 8 ty (4 samples each).
// Per j-step: 2 LDG.128 + 4 LDS + 4 FMUL + 32 FFMA  ->  32 useful FMA / ~42 slots.
__global__ void k_logits()
{
    int s0 = blockIdx.x * 32;
    int k  = blockIdx.y;                 // one 64x64 (i,j) block per CTA
    int tid = threadIdx.x, tx = tid % 16, ty = tid / 16;

    __shared__ float zh_s[32][BLK];
    __shared__ float zt_s[32][BLK];
    float acc[4][8] = {};

    // cooperative tile load: 32 rows x 64 floats = 512 float4 each, 4 per thread
    {
        int r  = tid / 4;                // 0..31
        int c16 = (tid % 4) * 16;        // 0,16,32,48
        const float* ph = g_zh + (size_t)(s0+r)*HH + k*BLK + c16;
        const float* pt = g_zt + (size_t)(s0+r)*HH + k*BLK + c16;
        #pragma unroll
        for (int u = 0; u < 4; ++u) {
            *(float4*)&zh_s[r][c16+4*u] = *(const float4*)(ph+4*u);
            *(float4*)&zt_s[r][c16+4*u] = *(const float4*)(pt+4*u);
        }
    }
    __syncthreads();

    for (int i = 0; i < BLK; ++i) {
        float zh_i[4];
        #pragma unroll
        for (int g = 0; g < 4; ++g) zh_i[g] = zh_s[ty + 8*g][i];   // LDS broadcast

        const float* wrow = g_Wc + (size_t)((k*BLK + i)*BLK)*NPAD + tx*8;
        #pragma unroll 4
        for (int j = 0; j < BLK; ++j) {
            float4 w0 = *(const float4*)(wrow + (size_t)j*NPAD);       // coalesced LDG.128
            float4 w1 = *(const float4*)(wrow + (size_t)j*NPAD + 4);
            #pragma unroll
            for (int g = 0; g < 4; ++g) {
                float a = zh_i[g] * zt_s[ty + 8*g][j];
                acc[g][0] += a*w0.x; acc[g][1] += a*w0.y;
                acc[g][2] += a*w0.z; acc[g][3] += a*w0.w;
                acc[g][4] += a*w1.x; acc[g][5] += a*w1.y;
                acc[g][6] += a*w1.z; acc[g][7] += a*w1.w;
            }
        }
    }

    float* pp = g_part + (size_t)k*NS*NCLS;
    #pragma unroll
    for (int g = 0; g < 4; ++g) {
        int s = s0 + ty + 8*g;
        #pragma unroll
        for (int c = 0; c < 8; ++c) {
            int n = tx*8 + c;
            if (n < NCLS) pp[(size_t)s*NCLS + n] = acc[g][c];
        }
    }
}

// ---------------- Kernel 7: reduce k-slice partials + bias -----------------------------
__global__ void k_reduce(const float* __restrict__ bcls, float* __restrict__ out)
{
    int idx = blockIdx.x*256 + threadIdx.x;
    if (idx >= NS*NCLS) return;
    int n = idx % NCLS;
    float v = bcls[n];
    #pragma unroll
    for (int sl = 0; sl < KSL; ++sl) v += g_part[(size_t)sl*NS*NCLS + idx];
    out[idx] = v;
}

// ---------------- launch: fork chain B (Wc) onto a side stream -------------------------
static cudaStream_t g_sB = 0;
static cudaEvent_t  g_evRoot = 0, g_evB = 0;

extern "C" void kernel_launch(void* const* d_in, const int* in_sizes, int n_in,
                              void* d_out, int out_size)
{
    (void)in_sizes; (void)n_in; (void)out_size;
    const float* seq   = (const float*)d_in[0];
    const float* att   = (const float*)d_in[1];
    const int*   mst   = (const int*)  d_in[2];
    const int*   cst   = (const int*)  d_in[3];
    const float* Wh    = (const float*)d_in[4];
    const float* bh    = (const float*)d_in[5];
    const float* Wt    = (const float*)d_in[6];
    const float* bt    = (const float*)d_in[7];
    const float* Wproj = (const float*)d_in[8];
    const float* Wcls  = (const float*)d_in[9];
    const float* bcls  = (const float*)d_in[10];
    float* out = (float*)d_out;

    // First (uncaptured correctness) call creates stream/events; capture call reuses.
    if (!g_sB) {
        cudaStreamCreateWithFlags(&g_sB, cudaStreamNonBlocking);
        cudaEventCreateWithFlags(&g_evRoot, cudaEventDisableTiming);
        cudaEventCreateWithFlags(&g_evB,    cudaEventDisableTiming);
    }

    // Fork: chain B = wclsT -> wc (depends only on kernel inputs)
    cudaEventRecord(g_evRoot, 0);
    cudaStreamWaitEvent(g_sB, g_evRoot, 0);
    k_wclsT<<<(HH*NPAD)/256, 256, 0, g_sB>>>(Wcls);
    k_wc<<<QTOT/64, 256, 0, g_sB>>>(Wproj);         // 768 CTAs
    cudaEventRecord(g_evB, g_sB);

    // Chain A on the main stream
    k_entity<<<BB*NE, 256>>>(seq, att, mst, cst);
    k_ht<<<BB*NE*NE, 256>>>();
    {
        dim3 g(NE*NE/64, HH/64, BB);                // 9 x 12 x 2
        k_rs<<<g, 256>>>(seq);
    }
    {
        dim3 g(HH/64, 2);                           // 12 x 2
        k_AhAt<<<g, 256>>>(Wh, bh, Wt, bt);
    }
    {
        dim3 g(NS/64, (2*HH)/64);                   // 18 x 24
        k_zhzt<<<g, 256>>>(Wh, Wt);
    }

    // Join, then the big product + reduce
    cudaStreamWaitEvent(0, g_evB, 0);
    {
        dim3 g(NS/32, KSL);                         // 36 x 12 = 432 CTAs
        k_logits<<<g, 128>>>();
    }
    k_reduce<<<(NS*NCLS + 255)/256, 256>>>(bcls, out);
}

// round 13
// speedup vs baseline: 1.2963x; 1.2310x over previous
#include <cuda_runtime.h>
#include <math.h>
#include <stdint.h>

// Problem constants
#define BB     2
#define LL     1024
#define HH     768
#define NHEADS 12
#define NE     24
#define MM     3
#define NC     2
#define CWW    8
#define BLK    64
#define NCLS   97
#define KB     12              // H / BLOCK
#define QTOT   (HH*BLK)        // 49152
#define NS     (BB*NE*NE)      // 1152
#define NPAD   128
#define KSL    12              // k-slices in logits kernel (one 64x64 block each)

// ---------------- device scratch (no runtime allocation allowed) ----------------
__device__ float g_eatt[BB*NE*NHEADS*LL];       // (b,e,h,l)  mean over mentions
__device__ float g_eemb[BB*NE*HH];              // logsumexp entity embedding
__device__ float g_ht[BB*NE*NE*LL];             // normalized relu attention product
__device__ float g_rs[(size_t)NS*HH];           // context vectors
__device__ float g_Ah[BB*NE*HH];                // e_emb @ Wh1^T + b_head
__device__ float g_At[BB*NE*HH];                // e_emb @ Wt1^T + b_tail
__device__ float g_zh[(size_t)NS*HH];
__device__ float g_zt[(size_t)NS*HH];
__device__ float g_WclsT[HH*NPAD];              // W_cls transposed, n-padded to 128
__device__ float g_Wc[(size_t)QTOT*NPAD];       // folded W_cls @ W_proj, layout [q][n]
__device__ float g_part[(size_t)KSL*NS*NCLS];   // logits partial sums per k-slice

// ---------------- Kernel 1: entity gather / gate / coref / logsumexp ----------------
__global__ void k_entity(const float* __restrict__ seq, const float* __restrict__ att,
                         const int* __restrict__ mst, const int* __restrict__ cst)
{
    int be  = blockIdx.x;           // b*NE + e
    int b   = be / NE;
    int tid = threadIdx.x;

    __shared__ float s_att[LL];
    __shared__ float s_gate[NC*CWW];
    __shared__ float s_red[256];
    __shared__ int   s_p[MM];
    __shared__ int   s_c[NC];

    if (tid < MM) s_p[tid] = mst[be*MM + tid] + 1;      // OFFSET = 1
    if (tid >= 32 && tid < 32+NC) s_c[tid-32] = cst[be*NC + (tid-32)];
    __syncthreads();

    int p0 = s_p[0], p1 = s_p[1], p2 = s_p[2];
    const float* ab = att + (size_t)b*NHEADS*LL*LL;

    for (int h = 0; h < NHEADS; ++h) {
        const float* r0 = ab + ((size_t)h*LL + p0)*LL;
        const float* r1 = ab + ((size_t)h*LL + p1)*LL;
        const float* r2 = ab + ((size_t)h*LL + p2)*LL;
        float* eo = g_eatt + ((size_t)be*NHEADS + h)*LL;
        for (int l = tid; l < LL; l += 256) {
            float v = (r0[l] + r1[l] + r2[l]) * (1.0f/3.0f);
            eo[l] = v;
            if (h == 0) s_att[l] = v; else s_att[l] += v;
        }
    }
    __syncthreads();

    float lsum = 0.f;
    for (int l = tid; l < LL; l += 256) lsum += s_att[l];
    s_red[tid] = lsum;
    __syncthreads();
    for (int off = 128; off > 0; off >>= 1) {
        if (tid < off) s_red[tid] += s_red[tid+off];
        __syncthreads();
    }
    float inv = 1.0f / s_red[0];

    if (tid < NC*CWW) {
        int c = tid / CWW, w = tid % CWW;
        s_gate[tid] = s_att[s_c[c] + w] * inv;
    }
    __syncthreads();

    const float* sb = seq + (size_t)b*LL*HH;
    int c0 = s_c[0], c1 = s_c[1];
    for (int d = tid; d < HH; d += 256) {
        float v0 = sb[(size_t)p0*HH + d];
        float v1 = sb[(size_t)p1*HH + d];
        float v2 = sb[(size_t)p2*HH + d];
        float v3 = 0.f, v4 = 0.f;
        #pragma unroll
        for (int w = 0; w < CWW; ++w) {
            v3 += s_gate[w]       * sb[(size_t)(c0+w)*HH + d];
            v4 += s_gate[CWW+w]   * sb[(size_t)(c1+w)*HH + d];
        }
        float mx = fmaxf(fmaxf(fmaxf(v0,v1), fmaxf(v2,v3)), v4);
        float s  = expf(v0-mx)+expf(v1-mx)+expf(v2-mx)+expf(v3-mx)+expf(v4-mx);
        g_eemb[(size_t)be*HH + d] = mx + logf(s);
    }
}

// ---------------- Kernel 2: ht = norm(relu(e_att . e_att^T over heads)) ----------------
__global__ void k_ht()
{
    int bef = blockIdx.x;                   // b*NE*NE + e*NE + f
    int b = bef / (NE*NE);
    int ef = bef % (NE*NE);
    int e = ef / NE, f = ef % NE;
    const float* pe = g_eatt + (size_t)(b*NE+e)*NHEADS*LL;
    const float* pf = g_eatt + (size_t)(b*NE+f)*NHEADS*LL;
    int tid = threadIdx.x;
    __shared__ float s_red[256];

    float v[4];
    float lsum = 0.f;
    #pragma unroll
    for (int r = 0; r < 4; ++r) {
        int l = r*256 + tid;
        float acc = 0.f;
        #pragma unroll
        for (int h = 0; h < NHEADS; ++h)
            acc += pe[h*LL + l] * pf[h*LL + l];
        v[r] = fmaxf(acc, 0.f);
        lsum += v[r];
    }
    s_red[tid] = lsum;
    __syncthreads();
    for (int off = 128; off > 0; off >>= 1) {
        if (tid < off) s_red[tid] += s_red[tid+off];
        __syncthreads();
    }
    float invn = 1.0f / (s_red[0] + 1e-10f);
    float* out = g_ht + (size_t)bef*LL;
    #pragma unroll
    for (int r = 0; r < 4; ++r) out[r*256 + tid] = v[r] * invn;
}

// ---------------- Kernel 3: rs[b] = ht[b] (576x1024) @ seq[b] (1024x768) ----------------
__global__ void k_rs(const float* __restrict__ seq)
{
    const int BM=64, BN=64, BK=16;
    int bm = blockIdx.x, bn = blockIdx.y, b = blockIdx.z;
    const float* A  = g_ht + (size_t)b*NE*NE*LL;
    const float* Bm = seq  + (size_t)b*LL*HH;
    __shared__ float As[BK][BM];
    __shared__ float Bs[BK][BN];
    int tid = threadIdx.x;
    int tx = tid % 16, ty = tid / 16;
    int arow = tid / 4,  acol4 = (tid % 4) * 4;
    int brow = tid / 16, bcol4 = (tid % 16) * 4;
    float acc[4][4] = {};

    for (int k0 = 0; k0 < LL; k0 += BK) {
        float4 a4 = *(const float4*)(A  + (size_t)(bm*BM + arow)*LL + k0 + acol4);
        float4 b4 = *(const float4*)(Bm + (size_t)(k0 + brow)*HH + bn*BN + bcol4);
        As[acol4+0][arow] = a4.x; As[acol4+1][arow] = a4.y;
        As[acol4+2][arow] = a4.z; As[acol4+3][arow] = a4.w;
        *(float4*)&Bs[brow][bcol4] = b4;
        __syncthreads();
        #pragma unroll
        for (int kk = 0; kk < BK; ++kk) {
            float4 av = *(float4*)&As[kk][ty*4];
            float4 bv = *(float4*)&Bs[kk][tx*4];
            acc[0][0]+=av.x*bv.x; acc[0][1]+=av.x*bv.y; acc[0][2]+=av.x*bv.z; acc[0][3]+=av.x*bv.w;
            acc[1][0]+=av.y*bv.x; acc[1][1]+=av.y*bv.y; acc[1][2]+=av.y*bv.z; acc[1][3]+=av.y*bv.w;
            acc[2][0]+=av.z*bv.x; acc[2][1]+=av.z*bv.y; acc[2][2]+=av.z*bv.z; acc[2][3]+=av.z*bv.w;
            acc[3][0]+=av.w*bv.x; acc[3][1]+=av.w*bv.y; acc[3][2]+=av.w*bv.z; acc[3][3]+=av.w*bv.w;
        }
        __syncthreads();
    }
    #pragma unroll
    for (int i = 0; i < 4; ++i) {
        float4 o = make_float4(acc[i][0], acc[i][1], acc[i][2], acc[i][3]);
        *(float4*)(g_rs + (size_t)(b*NE*NE + bm*BM + ty*4 + i)*HH + bn*BN + tx*4) = o;
    }
}

// ---------------- Kernel 4a: Ah/At = e_emb @ W1^T + bias (tiled GEMM, prefetched) -------
__global__ void k_AhAt(const float* __restrict__ Wh, const float* __restrict__ bh,
                       const float* __restrict__ Wt, const float* __restrict__ bt)
{
    const int BN = 64, BK = 16;
    int d0    = blockIdx.x * BN;
    int which = blockIdx.y;
    const float* W    = which ? Wt : Wh;
    const float* bias = which ? bt : bh;
    float* Out        = which ? g_At : g_Ah;

    __shared__ float e_s[BK][48+2];     // transposed: e_s[k][be]
    __shared__ float W_s[BK][BN+4];     // transposed: W_s[k][d]

    int tid = threadIdx.x;
    int tx = tid % 16, ty = tid / 16;   // tx -> 4 d's, ty -> 3 entities
    float acc[3][4] = {};

    int er = tid / 4,  ec4 = (tid % 4) * 4;
    int wr = tid / 4,  wc4 = (tid % 4) * 4;

    float4 e4 = make_float4(0,0,0,0), w4;
    if (tid < 192) e4 = *(const float4*)(g_eemb + (size_t)er*HH + ec4);
    w4 = *(const float4*)(W + (size_t)(d0+wr)*(2*HH) + wc4);

    for (int k0 = 0; k0 < HH; k0 += BK) {
        if (tid < 192) {
            e_s[ec4+0][er]=e4.x; e_s[ec4+1][er]=e4.y; e_s[ec4+2][er]=e4.z; e_s[ec4+3][er]=e4.w;
        }
        W_s[wc4+0][wr]=w4.x; W_s[wc4+1][wr]=w4.y; W_s[wc4+2][wr]=w4.z; W_s[wc4+3][wr]=w4.w;
        __syncthreads();
        if (k0 + BK < HH) {   // prefetch next tile while computing this one
            if (tid < 192) e4 = *(const float4*)(g_eemb + (size_t)er*HH + k0 + BK + ec4);
            w4 = *(const float4*)(W + (size_t)(d0+wr)*(2*HH) + k0 + BK + wc4);
        }
        #pragma unroll
        for (int kk = 0; kk < BK; ++kk) {
            float4 wv = *(float4*)&W_s[kk][tx*4];
            #pragma unroll
            for (int si = 0; si < 3; ++si) {
                float a = e_s[kk][ty*3 + si];
                acc[si][0]+=a*wv.x; acc[si][1]+=a*wv.y; acc[si][2]+=a*wv.z; acc[si][3]+=a*wv.w;
            }
        }
        __syncthreads();
    }
    #pragma unroll
    for (int si = 0; si < 3; ++si) {
        int be = ty*3 + si;
        #pragma unroll
        for (int c = 0; c < 4; ++c) {
            int d = d0 + tx*4 + c;
            Out[(size_t)be*HH + d] = acc[si][c] + bias[d];
        }
    }
}

// ---------------- Kernel 4b: [zh|zt] = tanh(rs @ W2^T + A) -----------------------------
__global__ void k_zhzt(const float* __restrict__ Wh, const float* __restrict__ Wt)
{
    const int BM=64, BN=64, BK=16;
    int bm = blockIdx.x, bn = blockIdx.y;
    bool isHead = (bn < HH/BN);
    const float* W = isHead ? Wh : Wt;
    int ncol0 = (isHead ? bn : bn - HH/BN) * BN;

    __shared__ float As[BK][BM];
    __shared__ float Bs[BK][BN];
    int tid = threadIdx.x;
    int tx = tid % 16, ty = tid / 16;
    int arow = tid / 4, acol4 = (tid % 4) * 4;
    float acc[4][4] = {};

    for (int k0 = 0; k0 < HH; k0 += BK) {
        float4 a4 = *(const float4*)(g_rs + (size_t)(bm*BM + arow)*HH + k0 + acol4);
        float4 b4 = *(const float4*)(W + (size_t)(ncol0 + arow)*(2*HH) + HH + k0 + acol4);
        As[acol4+0][arow] = a4.x; As[acol4+1][arow] = a4.y;
        As[acol4+2][arow] = a4.z; As[acol4+3][arow] = a4.w;
        Bs[acol4+0][arow] = b4.x; Bs[acol4+1][arow] = b4.y;
        Bs[acol4+2][arow] = b4.z; Bs[acol4+3][arow] = b4.w;
        __syncthreads();
        #pragma unroll
        for (int kk = 0; kk < BK; ++kk) {
            float4 av = *(float4*)&As[kk][ty*4];
            float4 bv = *(float4*)&Bs[kk][tx*4];
            acc[0][0]+=av.x*bv.x; acc[0][1]+=av.x*bv.y; acc[0][2]+=av.x*bv.z; acc[0][3]+=av.x*bv.w;
            acc[1][0]+=av.y*bv.x; acc[1][1]+=av.y*bv.y; acc[1][2]+=av.y*bv.z; acc[1][3]+=av.y*bv.w;
            acc[2][0]+=av.z*bv.x; acc[2][1]+=av.z*bv.y; acc[2][2]+=av.z*bv.z; acc[2][3]+=av.z*bv.w;
            acc[3][0]+=av.w*bv.x; acc[3][1]+=av.w*bv.y; acc[3][2]+=av.w*bv.z; acc[3][3]+=av.w*bv.w;
        }
        __syncthreads();
    }
    float* Z = isHead ? g_zh : g_zt;
    #pragma unroll
    for (int i = 0; i < 4; ++i) {
        int s  = bm*BM + ty*4 + i;
        int b  = s / (NE*NE);
        int ef = s % (NE*NE);
        int e  = ef / NE, f = ef % NE;
        const float* Avec = isHead ? (g_Ah + (size_t)(b*NE+e)*HH)
                                   : (g_At + (size_t)(b*NE+f)*HH);
        #pragma unroll
        for (int j = 0; j < 4; ++j) {
            int col = ncol0 + tx*4 + j;
            Z[(size_t)s*HH + col] = tanhf(acc[i][j] + Avec[col]);
        }
    }
}

// ---------------- Kernel 5a: transpose W_cls -> [d][n] padded to 128 -------------------
__global__ void k_wclsT(const float* __restrict__ Wcls)
{
    int idx = blockIdx.x*256 + threadIdx.x;
    if (idx >= HH*NPAD) return;
    int d = idx / NPAD, n = idx % NPAD;
    g_WclsT[idx] = (n < NCLS) ? Wcls[(size_t)n*HH + d] : 0.f;
}

// ---------------- Kernel 5b: Wc[q][n] = sum_d W_proj[d][q] * W_cls[n][d] ---------------
__global__ void k_wc(const float* __restrict__ Wproj)
{
    const int QT = 64, DB = 16;
    int q0 = blockIdx.x * QT;
    int tid = threadIdx.x, tx = tid % 32, ty = tid / 32;
    __shared__ float Wp_s[DB][QT];
    __shared__ float Wt_s[DB][NPAD];
    float acc[8][4] = {};

    int pr = tid / 16, pc4 = (tid % 16) * 4;    // Wp tile load map
    int cr = tid / 32, cc4 = (tid % 32) * 4;    // WclsT tile load map

    for (int d0 = 0; d0 < HH; d0 += DB) {
        *(float4*)&Wp_s[pr][pc4]   = *(const float4*)(Wproj + (size_t)(d0+pr)*QTOT + q0 + pc4);
        *(float4*)&Wt_s[cr][cc4]   = *(const float4*)(g_WclsT + (size_t)(d0+cr)*NPAD + cc4);
        *(float4*)&Wt_s[cr+8][cc4] = *(const float4*)(g_WclsT + (size_t)(d0+cr+8)*NPAD + cc4);
        __syncthreads();
        #pragma unroll
        for (int dd = 0; dd < DB; ++dd) {
            float4 wq0 = *(float4*)&Wp_s[dd][ty*8];
            float4 wq1 = *(float4*)&Wp_s[dd][ty*8+4];
            float4 wn  = *(float4*)&Wt_s[dd][tx*4];
            float wq[8] = {wq0.x,wq0.y,wq0.z,wq0.w,wq1.x,wq1.y,wq1.z,wq1.w};
            #pragma unroll
            for (int r = 0; r < 8; ++r) {
                acc[r][0] += wq[r]*wn.x;
                acc[r][1] += wq[r]*wn.y;
                acc[r][2] += wq[r]*wn.z;
                acc[r][3] += wq[r]*wn.w;
            }
        }
        __syncthreads();
    }
    #pragma unroll
    for (int r = 0; r < 8; ++r) {
        float4 o = make_float4(acc[r][0], acc[r][1], acc[r][2], acc[r][3]);
        *(float4*)(g_Wc + (size_t)(q0 + ty*8 + r)*NPAD + tx*4) = o;
    }
}

// ---------------- Kernel 6: logits partials = (zh (x) zt) . Wc -------------------------
// Barrier-free mainloop, 64-sample tile. Block 256 = 16 tx x 16 ty.
// Per thread: 4 samples (ty + 16*g) x 8 classes (tx*8..tx*8+7).
// Per j-step: 2 LDG.128 + 4 LDS + 4 FMUL + 32 FFMA -> 32/42 useful issue ratio.
__global__ void k_logits()
{
    int s0 = blockIdx.x * 64;
    int k  = blockIdx.y;                 // one 64x64 (i,j) block per CTA
    int tid = threadIdx.x, tx = tid % 16, ty = tid / 16;

    __shared__ float zh_s[64][BLK];
    __shared__ float zt_s[64][BLK];
    float acc[4][8] = {};

    // cooperative tile load: 64 rows x 64 floats each = 1024 float4 per array, 4/thread
    {
        int r   = tid / 4;               // 0..63
        int c16 = (tid % 4) * 16;        // 0,16,32,48
        const float* ph = g_zh + (size_t)(s0+r)*HH + k*BLK + c16;
        const float* pt = g_zt + (size_t)(s0+r)*HH + k*BLK + c16;
        #pragma unroll
        for (int u = 0; u < 4; ++u) {
            *(float4*)&zh_s[r][c16+4*u] = *(const float4*)(ph+4*u);
            *(float4*)&zt_s[r][c16+4*u] = *(const float4*)(pt+4*u);
        }
    }
    __syncthreads();

    for (int i = 0; i < BLK; ++i) {
        float zh_i[4];
        #pragma unroll
        for (int g = 0; g < 4; ++g) zh_i[g] = zh_s[ty + 16*g][i];   // LDS (amortized over j)

        const float* wrow = g_Wc + (size_t)((k*BLK + i)*BLK)*NPAD + tx*8;
        #pragma unroll 4
        for (int j = 0; j < BLK; ++j) {
            float4 w0 = *(const float4*)(wrow + (size_t)j*NPAD);       // coalesced LDG.128
            float4 w1 = *(const float4*)(wrow + (size_t)j*NPAD + 4);
            #pragma unroll
            for (int g = 0; g < 4; ++g) {
                float a = zh_i[g] * zt_s[ty + 16*g][j];                // LDS broadcast
                acc[g][0] += a*w0.x; acc[g][1] += a*w0.y;
                acc[g][2] += a*w0.z; acc[g][3] += a*w0.w;
                acc[g][4] += a*w1.x; acc[g][5] += a*w1.y;
                acc[g][6] += a*w1.z; acc[g][7] += a*w1.w;
            }
        }
    }

    float* pp = g_part + (size_t)k*NS*NCLS;
    #pragma unroll
    for (int g = 0; g < 4; ++g) {
        int s = s0 + ty + 16*g;
        #pragma unroll
        for (int c = 0; c < 8; ++c) {
            int n = tx*8 + c;
            if (n < NCLS) pp[(size_t)s*NCLS + n] = acc[g][c];
        }
    }
}

// ---------------- Kernel 7: reduce k-slice partials + bias -----------------------------
__global__ void k_reduce(const float* __restrict__ bcls, float* __restrict__ out)
{
    int idx = blockIdx.x*256 + threadIdx.x;
    if (idx >= NS*NCLS) return;
    int n = idx % NCLS;
    float v = bcls[n];
    #pragma unroll
    for (int sl = 0; sl < KSL; ++sl) v += g_part[(size_t)sl*NS*NCLS + idx];
    out[idx] = v;
}

// ---------------- launch (single stream, R8 order) -------------------------------------
extern "C" void kernel_launch(void* const* d_in, const int* in_sizes, int n_in,
                              void* d_out, int out_size)
{
    (void)in_sizes; (void)n_in; (void)out_size;
    const float* seq   = (const float*)d_in[0];
    const float* att   = (const float*)d_in[1];
    const int*   mst   = (const int*)  d_in[2];
    const int*   cst   = (const int*)  d_in[3];
    const float* Wh    = (const float*)d_in[4];
    const float* bh    = (const float*)d_in[5];
    const float* Wt    = (const float*)d_in[6];
    const float* bt    = (const float*)d_in[7];
    const float* Wproj = (const float*)d_in[8];
    const float* Wcls  = (const float*)d_in[9];
    const float* bcls  = (const float*)d_in[10];
    float* out = (float*)d_out;

    k_entity<<<BB*NE, 256>>>(seq, att, mst, cst);
    k_ht<<<BB*NE*NE, 256>>>();
    {
        dim3 g(NE*NE/64, HH/64, BB);            // 9 x 12 x 2
        k_rs<<<g, 256>>>(seq);
    }
    {
        dim3 g(HH/64, 2);                       // 12 x 2
        k_AhAt<<<g, 256>>>(Wh, bh, Wt, bt);
    }
    {
        dim3 g(NS/64, (2*HH)/64);               // 18 x 24
        k_zhzt<<<g, 256>>>(Wh, Wt);
    }
    k_wclsT<<<(HH*NPAD)/256, 256>>>(Wcls);
    k_wc<<<QTOT/64, 256>>>(Wproj);              // 768 CTAs
    {
        dim3 g(NS/64, KSL);                     // 18 x 12 = 216 CTAs
        k_logits<<<g, 256>>>();
    }
    k_reduce<<<(NS*NCLS + 255)/256, 256>>>(bcls, out);
}

// round 14
// speedup vs baseline: 1.6249x; 1.2535x over previous
#include <cuda_runtime.h>
#include <math.h>
#include <stdint.h>

// Problem constants
#define BB     2
#define LL     1024
#define HH     768
#define NHEADS 12
#define NE     24
#define MM     3
#define NC     2
#define CWW    8
#define BLK    64
#define NCLS   97
#define KB     12              // H / BLOCK
#define QTOT   (HH*BLK)        // 49152
#define NS     (BB*NE*NE)      // 1152
#define NPAD   128
#define KSL    12              // k-slices in logits kernel (one 64x64 block each)
#define ZSTR   (BLK+4)         // padded smem row stride (68): Δrow=1 -> 4-bank offset

// ---------------- device scratch (no runtime allocation allowed) ----------------
__device__ float g_eatt[BB*NE*NHEADS*LL];       // (b,e,h,l)  mean over mentions
__device__ float g_eemb[BB*NE*HH];              // logsumexp entity embedding
__device__ float g_ht[BB*NE*NE*LL];             // normalized relu attention product
__device__ float g_rs[(size_t)NS*HH];           // context vectors
__device__ float g_Ah[BB*NE*HH];                // e_emb @ Wh1^T + b_head
__device__ float g_At[BB*NE*HH];                // e_emb @ Wt1^T + b_tail
__device__ float g_zh[(size_t)NS*HH];
__device__ float g_zt[(size_t)NS*HH];
__device__ float g_WclsT[HH*NPAD];              // W_cls transposed, n-padded to 128
__device__ float g_Wc[(size_t)QTOT*NPAD];       // folded W_cls @ W_proj, layout [q][n]
__device__ float g_part[(size_t)KSL*NS*NCLS];   // logits partial sums per k-slice

// ---------------- Kernel 1: entity gather / gate / coref / logsumexp ----------------
__global__ void k_entity(const float* __restrict__ seq, const float* __restrict__ att,
                         const int* __restrict__ mst, const int* __restrict__ cst)
{
    int be  = blockIdx.x;           // b*NE + e
    int b   = be / NE;
    int tid = threadIdx.x;

    __shared__ float s_att[LL];
    __shared__ float s_gate[NC*CWW];
    __shared__ float s_red[256];
    __shared__ int   s_p[MM];
    __shared__ int   s_c[NC];

    if (tid < MM) s_p[tid] = mst[be*MM + tid] + 1;      // OFFSET = 1
    if (tid >= 32 && tid < 32+NC) s_c[tid-32] = cst[be*NC + (tid-32)];
    __syncthreads();

    int p0 = s_p[0], p1 = s_p[1], p2 = s_p[2];
    const float* ab = att + (size_t)b*NHEADS*LL*LL;

    for (int h = 0; h < NHEADS; ++h) {
        const float* r0 = ab + ((size_t)h*LL + p0)*LL;
        const float* r1 = ab + ((size_t)h*LL + p1)*LL;
        const float* r2 = ab + ((size_t)h*LL + p2)*LL;
        float* eo = g_eatt + ((size_t)be*NHEADS + h)*LL;
        for (int l = tid; l < LL; l += 256) {
            float v = (r0[l] + r1[l] + r2[l]) * (1.0f/3.0f);
            eo[l] = v;
            if (h == 0) s_att[l] = v; else s_att[l] += v;
        }
    }
    __syncthreads();

    float lsum = 0.f;
    for (int l = tid; l < LL; l += 256) lsum += s_att[l];
    s_red[tid] = lsum;
    __syncthreads();
    for (int off = 128; off > 0; off >>= 1) {
        if (tid < off) s_red[tid] += s_red[tid+off];
        __syncthreads();
    }
    float inv = 1.0f / s_red[0];

    if (tid < NC*CWW) {
        int c = tid / CWW, w = tid % CWW;
        s_gate[tid] = s_att[s_c[c] + w] * inv;
    }
    __syncthreads();

    const float* sb = seq + (size_t)b*LL*HH;
    int c0 = s_c[0], c1 = s_c[1];
    for (int d = tid; d < HH; d += 256) {
        float v0 = sb[(size_t)p0*HH + d];
        float v1 = sb[(size_t)p1*HH + d];
        float v2 = sb[(size_t)p2*HH + d];
        float v3 = 0.f, v4 = 0.f;
        #pragma unroll
        for (int w = 0; w < CWW; ++w) {
            v3 += s_gate[w]       * sb[(size_t)(c0+w)*HH + d];
            v4 += s_gate[CWW+w]   * sb[(size_t)(c1+w)*HH + d];
        }
        float mx = fmaxf(fmaxf(fmaxf(v0,v1), fmaxf(v2,v3)), v4);
        float s  = expf(v0-mx)+expf(v1-mx)+expf(v2-mx)+expf(v3-mx)+expf(v4-mx);
        g_eemb[(size_t)be*HH + d] = mx + logf(s);
    }
}

// ---------------- Kernel 2: ht = norm(relu(e_att . e_att^T over heads)) ----------------
__global__ void k_ht()
{
    int bef = blockIdx.x;                   // b*NE*NE + e*NE + f
    int b = bef / (NE*NE);
    int ef = bef % (NE*NE);
    int e = ef / NE, f = ef % NE;
    const float* pe = g_eatt + (size_t)(b*NE+e)*NHEADS*LL;
    const float* pf = g_eatt + (size_t)(b*NE+f)*NHEADS*LL;
    int tid = threadIdx.x;
    __shared__ float s_red[256];

    float v[4];
    float lsum = 0.f;
    #pragma unroll
    for (int r = 0; r < 4; ++r) {
        int l = r*256 + tid;
        float acc = 0.f;
        #pragma unroll
        for (int h = 0; h < NHEADS; ++h)
            acc += pe[h*LL + l] * pf[h*LL + l];
        v[r] = fmaxf(acc, 0.f);
        lsum += v[r];
    }
    s_red[tid] = lsum;
    __syncthreads();
    for (int off = 128; off > 0; off >>= 1) {
        if (tid < off) s_red[tid] += s_red[tid+off];
        __syncthreads();
    }
    float invn = 1.0f / (s_red[0] + 1e-10f);
    float* out = g_ht + (size_t)bef*LL;
    #pragma unroll
    for (int r = 0; r < 4; ++r) out[r*256 + tid] = v[r] * invn;
}

// ---------------- Kernel 3: rs[b] = ht[b] (576x1024) @ seq[b] (1024x768) ----------------
__global__ void k_rs(const float* __restrict__ seq)
{
    const int BM=64, BN=64, BK=16;
    int bm = blockIdx.x, bn = blockIdx.y, b = blockIdx.z;
    const float* A  = g_ht + (size_t)b*NE*NE*LL;
    const float* Bm = seq  + (size_t)b*LL*HH;
    __shared__ float As[BK][BM];
    __shared__ float Bs[BK][BN];
    int tid = threadIdx.x;
    int tx = tid % 16, ty = tid / 16;
    int arow = tid / 4,  acol4 = (tid % 4) * 4;
    int brow = tid / 16, bcol4 = (tid % 16) * 4;
    float acc[4][4] = {};

    for (int k0 = 0; k0 < LL; k0 += BK) {
        float4 a4 = *(const float4*)(A  + (size_t)(bm*BM + arow)*LL + k0 + acol4);
        float4 b4 = *(const float4*)(Bm + (size_t)(k0 + brow)*HH + bn*BN + bcol4);
        As[acol4+0][arow] = a4.x; As[acol4+1][arow] = a4.y;
        As[acol4+2][arow] = a4.z; As[acol4+3][arow] = a4.w;
        *(float4*)&Bs[brow][bcol4] = b4;
        __syncthreads();
        #pragma unroll
        for (int kk = 0; kk < BK; ++kk) {
            float4 av = *(float4*)&As[kk][ty*4];
            float4 bv = *(float4*)&Bs[kk][tx*4];
            acc[0][0]+=av.x*bv.x; acc[0][1]+=av.x*bv.y; acc[0][2]+=av.x*bv.z; acc[0][3]+=av.x*bv.w;
            acc[1][0]+=av.y*bv.x; acc[1][1]+=av.y*bv.y; acc[1][2]+=av.y*bv.z; acc[1][3]+=av.y*bv.w;
            acc[2][0]+=av.z*bv.x; acc[2][1]+=av.z*bv.y; acc[2][2]+=av.z*bv.z; acc[2][3]+=av.z*bv.w;
            acc[3][0]+=av.w*bv.x; acc[3][1]+=av.w*bv.y; acc[3][2]+=av.w*bv.z; acc[3][3]+=av.w*bv.w;
        }
        __syncthreads();
    }
    #pragma unroll
    for (int i = 0; i < 4; ++i) {
        float4 o = make_float4(acc[i][0], acc[i][1], acc[i][2], acc[i][3]);
        *(float4*)(g_rs + (size_t)(b*NE*NE + bm*BM + ty*4 + i)*HH + bn*BN + tx*4) = o;
    }
}

// ---------------- Kernel 4a: Ah/At = e_emb @ W1^T + bias (tiled GEMM, prefetched) -------
__global__ void k_AhAt(const float* __restrict__ Wh, const float* __restrict__ bh,
                       const float* __restrict__ Wt, const float* __restrict__ bt)
{
    const int BN = 64, BK = 16;
    int d0    = blockIdx.x * BN;
    int which = blockIdx.y;
    const float* W    = which ? Wt : Wh;
    const float* bias = which ? bt : bh;
    float* Out        = which ? g_At : g_Ah;

    __shared__ float e_s[BK][48+2];     // transposed: e_s[k][be]
    __shared__ float W_s[BK][BN+4];     // transposed: W_s[k][d]

    int tid = threadIdx.x;
    int tx = tid % 16, ty = tid / 16;   // tx -> 4 d's, ty -> 3 entities
    float acc[3][4] = {};

    int er = tid / 4,  ec4 = (tid % 4) * 4;
    int wr = tid / 4,  wc4 = (tid % 4) * 4;

    float4 e4 = make_float4(0,0,0,0), w4;
    if (tid < 192) e4 = *(const float4*)(g_eemb + (size_t)er*HH + ec4);
    w4 = *(const float4*)(W + (size_t)(d0+wr)*(2*HH) + wc4);

    for (int k0 = 0; k0 < HH; k0 += BK) {
        if (tid < 192) {
            e_s[ec4+0][er]=e4.x; e_s[ec4+1][er]=e4.y; e_s[ec4+2][er]=e4.z; e_s[ec4+3][er]=e4.w;
        }
        W_s[wc4+0][wr]=w4.x; W_s[wc4+1][wr]=w4.y; W_s[wc4+2][wr]=w4.z; W_s[wc4+3][wr]=w4.w;
        __syncthreads();
        if (k0 + BK < HH) {   // prefetch next tile while computing this one
            if (tid < 192) e4 = *(const float4*)(g_eemb + (size_t)er*HH + k0 + BK + ec4);
            w4 = *(const float4*)(W + (size_t)(d0+wr)*(2*HH) + k0 + BK + wc4);
        }
        #pragma unroll
        for (int kk = 0; kk < BK; ++kk) {
            float4 wv = *(float4*)&W_s[kk][tx*4];
            #pragma unroll
            for (int si = 0; si < 3; ++si) {
                float a = e_s[kk][ty*3 + si];
                acc[si][0]+=a*wv.x; acc[si][1]+=a*wv.y; acc[si][2]+=a*wv.z; acc[si][3]+=a*wv.w;
            }
        }
        __syncthreads();
    }
    #pragma unroll
    for (int si = 0; si < 3; ++si) {
        int be = ty*3 + si;
        #pragma unroll
        for (int c = 0; c < 4; ++c) {
            int d = d0 + tx*4 + c;
            Out[(size_t)be*HH + d] = acc[si][c] + bias[d];
        }
    }
}

// ---------------- Kernel 4b: [zh|zt] = tanh(rs @ W2^T + A) -----------------------------
__global__ void k_zhzt(const float* __restrict__ Wh, const float* __restrict__ Wt)
{
    const int BM=64, BN=64, BK=16;
    int bm = blockIdx.x, bn = blockIdx.y;
    bool isHead = (bn < HH/BN);
    const float* W = isHead ? Wh : Wt;
    int ncol0 = (isHead ? bn : bn - HH/BN) * BN;

    __shared__ float As[BK][BM];
    __shared__ float Bs[BK][BN];
    int tid = threadIdx.x;
    int tx = tid % 16, ty = tid / 16;
    int arow = tid / 4, acol4 = (tid % 4) * 4;
    float acc[4][4] = {};

    for (int k0 = 0; k0 < HH; k0 += BK) {
        float4 a4 = *(const float4*)(g_rs + (size_t)(bm*BM + arow)*HH + k0 + acol4);
        float4 b4 = *(const float4*)(W + (size_t)(ncol0 + arow)*(2*HH) + HH + k0 + acol4);
        As[acol4+0][arow] = a4.x; As[acol4+1][arow] = a4.y;
        As[acol4+2][arow] = a4.z; As[acol4+3][arow] = a4.w;
        Bs[acol4+0][arow] = b4.x; Bs[acol4+1][arow] = b4.y;
        Bs[acol4+2][arow] = b4.z; Bs[acol4+3][arow] = b4.w;
        __syncthreads();
        #pragma unroll
        for (int kk = 0; kk < BK; ++kk) {
            float4 av = *(float4*)&As[kk][ty*4];
            float4 bv = *(float4*)&Bs[kk][tx*4];
            acc[0][0]+=av.x*bv.x; acc[0][1]+=av.x*bv.y; acc[0][2]+=av.x*bv.z; acc[0][3]+=av.x*bv.w;
            acc[1][0]+=av.y*bv.x; acc[1][1]+=av.y*bv.y; acc[1][2]+=av.y*bv.z; acc[1][3]+=av.y*bv.w;
            acc[2][0]+=av.z*bv.x; acc[2][1]+=av.z*bv.y; acc[2][2]+=av.z*bv.z; acc[2][3]+=av.z*bv.w;
            acc[3][0]+=av.w*bv.x; acc[3][1]+=av.w*bv.y; acc[3][2]+=av.w*bv.z; acc[3][3]+=av.w*bv.w;
        }
        __syncthreads();
    }
    float* Z = isHead ? g_zh : g_zt;
    #pragma unroll
    for (int i = 0; i < 4; ++i) {
        int s  = bm*BM + ty*4 + i;
        int b  = s / (NE*NE);
        int ef = s % (NE*NE);
        int e  = ef / NE, f = ef % NE;
        const float* Avec = isHead ? (g_Ah + (size_t)(b*NE+e)*HH)
                                   : (g_At + (size_t)(b*NE+f)*HH);
        #pragma unroll
        for (int j = 0; j < 4; ++j) {
            int col = ncol0 + tx*4 + j;
            Z[(size_t)s*HH + col] = tanhf(acc[i][j] + Avec[col]);
        }
    }
}

// ---------------- Kernel 5a: transpose W_cls -> [d][n] padded to 128 -------------------
__global__ void k_wclsT(const float* __restrict__ Wcls)
{
    int idx = blockIdx.x*256 + threadIdx.x;
    if (idx >= HH*NPAD) return;
    int d = idx / NPAD, n = idx % NPAD;
    g_WclsT[idx] = (n < NCLS) ? Wcls[(size_t)n*HH + d] : 0.f;
}

// ---------------- Kernel 5b: Wc[q][n] = sum_d W_proj[d][q] * W_cls[n][d] ---------------
__global__ void k_wc(const float* __restrict__ Wproj)
{
    const int QT = 64, DB = 16;
    int q0 = blockIdx.x * QT;
    int tid = threadIdx.x, tx = tid % 32, ty = tid / 32;
    __shared__ float Wp_s[DB][QT];
    __shared__ float Wt_s[DB][NPAD];
    float acc[8][4] = {};

    int pr = tid / 16, pc4 = (tid % 16) * 4;    // Wp tile load map
    int cr = tid / 32, cc4 = (tid % 32) * 4;    // WclsT tile load map

    for (int d0 = 0; d0 < HH; d0 += DB) {
        *(float4*)&Wp_s[pr][pc4]   = *(const float4*)(Wproj + (size_t)(d0+pr)*QTOT + q0 + pc4);
        *(float4*)&Wt_s[cr][cc4]   = *(const float4*)(g_WclsT + (size_t)(d0+cr)*NPAD + cc4);
        *(float4*)&Wt_s[cr+8][cc4] = *(const float4*)(g_WclsT + (size_t)(d0+cr+8)*NPAD + cc4);
        __syncthreads();
        #pragma unroll
        for (int dd = 0; dd < DB; ++dd) {
            float4 wq0 = *(float4*)&Wp_s[dd][ty*8];
            float4 wq1 = *(float4*)&Wp_s[dd][ty*8+4];
            float4 wn  = *(float4*)&Wt_s[dd][tx*4];
            float wq[8] = {wq0.x,wq0.y,wq0.z,wq0.w,wq1.x,wq1.y,wq1.z,wq1.w};
            #pragma unroll
            for (int r = 0; r < 8; ++r) {
                acc[r][0] += wq[r]*wn.x;
                acc[r][1] += wq[r]*wn.y;
                acc[r][2] += wq[r]*wn.z;
                acc[r][3] += wq[r]*wn.w;
            }
        }
        __syncthreads();
    }
    #pragma unroll
    for (int r = 0; r < 8; ++r) {
        float4 o = make_float4(acc[r][0], acc[r][1], acc[r][2], acc[r][3]);
        *(float4*)(g_Wc + (size_t)(q0 + ty*8 + r)*NPAD + tx*4) = o;
    }
}

// ---------------- Kernel 6: logits partials = (zh (x) zt) . Wc -------------------------
// Barrier-free mainloop. 32-sample tile, block 128 = 16 tx x 8 ty.
// Per thread: 4 samples (ty + 8*g) x 8 classes (tx*8..tx*8+7).
// Smem rows padded to ZSTR=68 floats: warp spans ty,ty+1 -> bank offset 4 (no conflict).
// Per j-step: 2 LDG.128 + 4 LDS + 4 FMUL + 32 FFMA -> ~1.37 issue slots per useful FFMA.
__global__ void k_logits()
{
    int s0 = blockIdx.x * 32;
    int k  = blockIdx.y;                 // one 64x64 (i,j) block per CTA
    int tid = threadIdx.x, tx = tid % 16, ty = tid / 16;

    __shared__ float zh_s[32][ZSTR];
    __shared__ float zt_s[32][ZSTR];
    float acc[4][8] = {};

    // cooperative tile load: 32 rows x 64 floats = 512 float4 per array, 4/thread each
    {
        int r   = tid / 4;               // 0..31
        int c16 = (tid % 4) * 16;        // 0,16,32,48
        const float* ph = g_zh + (size_t)(s0+r)*HH + k*BLK + c16;
        const float* pt = g_zt + (size_t)(s0+r)*HH + k*BLK + c16;
        #pragma unroll
        for (int u = 0; u < 4; ++u) {
            *(float4*)&zh_s[r][c16+4*u] = *(const float4*)(ph+4*u);
            *(float4*)&zt_s[r][c16+4*u] = *(const float4*)(pt+4*u);
        }
    }
    __syncthreads();

    for (int i = 0; i < BLK; ++i) {
        float zh_i[4];
        #pragma unroll
        for (int g = 0; g < 4; ++g) zh_i[g] = zh_s[ty + 8*g][i];    // amortized over j

        const float* wrow = g_Wc + (size_t)((k*BLK + i)*BLK)*NPAD + tx*8;
        #pragma unroll 4
        for (int j = 0; j < BLK; ++j) {
            float4 w0 = *(const float4*)(wrow + (size_t)j*NPAD);        // coalesced LDG.128
            float4 w1 = *(const float4*)(wrow + (size_t)j*NPAD + 4);
            #pragma unroll
            for (int g = 0; g < 4; ++g) {
                float a = zh_i[g] * zt_s[ty + 8*g][j];                  // conflict-free LDS
                acc[g][0] += a*w0.x; acc[g][1] += a*w0.y;
                acc[g][2] += a*w0.z; acc[g][3] += a*w0.w;
                acc[g][4] += a*w1.x; acc[g][5] += a*w1.y;
                acc[g][6] += a*w1.z; acc[g][7] += a*w1.w;
            }
        }
    }

    float* pp = g_part + (size_t)k*NS*NCLS;
    #pragma unroll
    for (int g = 0; g < 4; ++g) {
        int s = s0 + ty + 8*g;
        #pragma unroll
        for (int c = 0; c < 8; ++c) {
            int n = tx*8 + c;
            if (n < NCLS) pp[(size_t)s*NCLS + n] = acc[g][c];
        }
    }
}

// ---------------- Kernel 7: reduce k-slice partials + bias -----------------------------
__global__ void k_reduce(const float* __restrict__ bcls, float* __restrict__ out)
{
    int idx = blockIdx.x*256 + threadIdx.x;
    if (idx >= NS*NCLS) return;
    int n = idx % NCLS;
    float v = bcls[n];
    #pragma unroll
    for (int sl = 0; sl < KSL; ++sl) v += g_part[(size_t)sl*NS*NCLS + idx];
    out[idx] = v;
}

// ---------------- launch (single stream, R8 order) -------------------------------------
extern "C" void kernel_launch(void* const* d_in, const int* in_sizes, int n_in,
                              void* d_out, int out_size)
{
    (void)in_sizes; (void)n_in; (void)out_size;
    const float* seq   = (const float*)d_in[0];
    const float* att   = (const float*)d_in[1];
    const int*   mst   = (const int*)  d_in[2];
    const int*   cst   = (const int*)  d_in[3];
    const float* Wh    = (const float*)d_in[4];
    const float* bh    = (const float*)d_in[5];
    const float* Wt    = (const float*)d_in[6];
    const float* bt    = (const float*)d_in[7];
    const float* Wproj = (const float*)d_in[8];
    const float* Wcls  = (const float*)d_in[9];
    const float* bcls  = (const float*)d_in[10];
    float* out = (float*)d_out;

    k_entity<<<BB*NE, 256>>>(seq, att, mst, cst);
    k_ht<<<BB*NE*NE, 256>>>();
    {
        dim3 g(NE*NE/64, HH/64, BB);            // 9 x 12 x 2
        k_rs<<<g, 256>>>(seq);
    }
    {
        dim3 g(HH/64, 2);                       // 12 x 2
        k_AhAt<<<g, 256>>>(Wh, bh, Wt, bt);
    }
    {
        dim3 g(NS/64, (2*HH)/64);               // 18 x 24
        k_zhzt<<<g, 256>>>(Wh, Wt);
    }
    k_wclsT<<<(HH*NPAD)/256, 256>>>(Wcls);
    k_wc<<<QTOT/64, 256>>>(Wproj);              // 768 CTAs
    {
        dim3 g(NS/32, KSL);                     // 36 x 12 = 432 CTAs
        k_logits<<<g, 128>>>();
    }
    k_reduce<<<(NS*NCLS + 255)/256, 256>>>(bcls, out);
}